// round 15
// baseline (speedup 1.0000x reference)
#include <cuda_runtime.h>
#include <cuda_bf16.h>
#include <cstdint>

#define DIM   128
#define MAX_N 50000
#define MAX_E 800000

#define GEMM_RPB 128
#define AS 20                 // smem row stride in u32 words (32 bf16 = 16w + 4 pad)
#define BUFU (4 * 128 * AS)   // u32 per pipeline buffer (a_hi,a_lo,w_hi,w_lo)
#define SMEM_DYN (2 * BUFU * 4)
#define QSCALE 4096.0f
#define QINV   (1.0f / 4096.0f)

// ---------------------------------------------------------------------------
// Scratch (no allocations allowed). g_deg/g_total rely on zero-init at load;
// they are re-zeroed at the end of every launch (layer-2 aggregate).
// ---------------------------------------------------------------------------
__device__ __align__(16) __nv_bfloat16 g_xhi[MAX_N * DIM];
__device__ __align__(16) __nv_bfloat16 g_xlo[MAX_N * DIM];
__device__ __align__(16) __nv_bfloat16 g_hhi[MAX_N * DIM];
__device__ __align__(16) __nv_bfloat16 g_hlo[MAX_N * DIM];
__device__ __align__(16) __nv_bfloat16 g_ahi[MAX_N * DIM];
__device__ __align__(16) __nv_bfloat16 g_alo[MAX_N * DIM];
__device__ __align__(16) short g_xq[MAX_N * DIM];   // int16 features, scale 4096
__device__ __align__(16) short g_hq[MAX_N * DIM];
__device__ __align__(16) __nv_bfloat16 g_wthi[2 * DIM * 2 * DIM]; // [layer][n][k]
__device__ __align__(16) __nv_bfloat16 g_wtlo[2 * DIM * 2 * DIM];
__device__ int g_deg[MAX_N];     // zero at launch start (invariant)
__device__ int g_row[MAX_N];
__device__ int g_pos[MAX_E];
__device__ int g_csr[MAX_E];     // element offsets: src_node * DIM
__device__ int g_total;          // zero at launch start (invariant)

// ---------------------------------------------------------------------------
// Helpers
// ---------------------------------------------------------------------------
__device__ __forceinline__ uint32_t pack_bf2(float a, float b) {
    __nv_bfloat162 t = __floats2bfloat162_rn(a, b);
    return *reinterpret_cast<uint32_t*>(&t);
}
__device__ __forceinline__ void split1(float v, float& hi, float& lo) {
    __nv_bfloat16 h = __float2bfloat16_rn(v);
    hi = __bfloat162float(h);
    lo = v - hi;
}
__device__ __forceinline__ int quant1(float v) {
    return __float2int_rn(fminf(fmaxf(v * QSCALE, -32767.0f), 32767.0f));
}
__device__ __forceinline__ uint32_t pack_q2(float a, float b) {
    return (uint32_t)(quant1(a) & 0xffff) | ((uint32_t)quant1(b) << 16);
}
__device__ __forceinline__ void mma_bf16(float* d, const uint32_t* a,
                                         const uint32_t* b) {
    asm volatile(
        "mma.sync.aligned.m16n8k16.row.col.f32.bf16.bf16.f32 "
        "{%0,%1,%2,%3}, {%4,%5,%6,%7}, {%8,%9}, {%0,%1,%2,%3};"
        : "+f"(d[0]), "+f"(d[1]), "+f"(d[2]), "+f"(d[3])
        : "r"(a[0]), "r"(a[1]), "r"(a[2]), "r"(a[3]), "r"(b[0]), "r"(b[1]));
}
__device__ __forceinline__ void cp16(uint32_t dst_smem, const void* src, int sz) {
    asm volatile("cp.async.cg.shared.global [%0], [%1], 16, %2;"
                 :: "r"(dst_smem), "l"(src), "r"(sz));
}
// s += sign_extend(lo16(v)) / sign_extend(hi16(v)) : one dp2a each
__device__ __forceinline__ int acc_lo(uint32_t v, int s) {
    return __dp2a_lo((int)v, 1, s);
}
__device__ __forceinline__ int acc_hi(uint32_t v, int s) {
    return __dp2a_lo((int)v, 256, s);
}

// ---------------------------------------------------------------------------
// Fused prep: degree count (g_deg pre-zeroed invariant) + split x + split W
// ---------------------------------------------------------------------------
__global__ void prep_kernel(const float* __restrict__ X,
                            const float* __restrict__ W1,
                            const float* __restrict__ W2,
                            const int* __restrict__ tgt,
                            int E, int n_nodes, int n4) {
    int i = blockIdx.x * blockDim.x + threadIdx.x;
    if (i < E) {
        int d = tgt[i];
        if ((unsigned)d < (unsigned)n_nodes)
            g_pos[i] = atomicAdd(&g_deg[d], 1);
    }
    if (i < n4) {
        float4 v = reinterpret_cast<const float4*>(X)[i];
        float hx, lx, hy, ly, hz, lz, hw, lw;
        split1(v.x, hx, lx); split1(v.y, hy, ly);
        split1(v.z, hz, lz); split1(v.w, hw, lw);
        reinterpret_cast<uint2*>(g_xhi)[i] = make_uint2(pack_bf2(hx, hy), pack_bf2(hz, hw));
        reinterpret_cast<uint2*>(g_xlo)[i] = make_uint2(pack_bf2(lx, ly), pack_bf2(lz, lw));
        reinterpret_cast<uint2*>(g_xq)[i]  = make_uint2(pack_q2(v.x, v.y), pack_q2(v.z, v.w));
    }
    if (i < 2 * 256 * 128) {
        int layer = i >> 15;
        int idx = i & 32767;
        int k = idx >> 7;
        int n = idx & 127;
        float v = layer ? W2[idx] : W1[idx];
        float hi, lo;
        split1(v, hi, lo);
        size_t o = (size_t)layer * DIM * 2 * DIM + (size_t)n * 2 * DIM + k;
        g_wthi[o] = __float2bfloat16_rn(hi);
        g_wtlo[o] = __float2bfloat16_rn(lo);
    }
}

// ---------------------------------------------------------------------------
// CSR construction
// ---------------------------------------------------------------------------
__global__ void reserve_kernel(int n_nodes) {
    int i = blockIdx.x * blockDim.x + threadIdx.x;
    if (i < n_nodes) g_row[i] = atomicAdd(&g_total, g_deg[i]);
}

__global__ void fill_kernel(const int* __restrict__ src,
                            const int* __restrict__ tgt, int E, int n_nodes) {
    int e = blockIdx.x * blockDim.x + threadIdx.x;
    if (e < E) {
        int d = tgt[e];
        if ((unsigned)d < (unsigned)n_nodes) {
            int s = src[e];
            s = min(max(s, 0), n_nodes - 1);
            g_csr[g_row[d] + g_pos[e]] = s * DIM;   // element offset
        }
    }
}

// ---------------------------------------------------------------------------
// Aggregation: one warp per node; half-warp per neighbor row (LDG.128).
// Lanes 0-15 gather neighbor j, lanes 16-31 neighbor j+1; each lane owns
// 8 int16 elements; exact int32 accumulation via dp2a; shfl_xor(16) combine.
// Layer-2 pass (use_h=1) re-zeroes g_deg/g_total to restore launch invariant.
// ---------------------------------------------------------------------------
__global__ void aggregate_kernel(int use_h, int n_nodes) {
    int warp = (blockIdx.x * blockDim.x + threadIdx.x) >> 5;
    int lane = threadIdx.x & 31;
    if (warp >= n_nodes) return;

    const short* __restrict__ Xq = use_h ? g_hq : g_xq;
    const int* __restrict__ csr = g_csr;
    const int base = g_row[warp];
    const int deg  = g_deg[warp];
    const int half  = lane >> 4;
    const int lid16 = lane & 15;
    const int coloff = lid16 * 8;      // short offset within row

    if (use_h && lane == 0) {
        g_deg[warp] = 0;               // restore zero invariant
        if (warp == 0) g_total = 0;
    }

    int s0 = 0, s1 = 0, s2 = 0, s3 = 0, s4 = 0, s5 = 0, s6 = 0, s7 = 0;
    int j = 0;
    for (; j + 8 <= deg; j += 8) {
        uint4 v[4];
#pragma unroll
        for (int b = 0; b < 4; b++) {
            int off = __ldg(&csr[base + j + 2 * b + half]);
            v[b] = *reinterpret_cast<const uint4*>(Xq + (size_t)off + coloff);
        }
#pragma unroll
        for (int b = 0; b < 4; b++) {
            s0 = acc_lo(v[b].x, s0); s1 = acc_hi(v[b].x, s1);
            s2 = acc_lo(v[b].y, s2); s3 = acc_hi(v[b].y, s3);
            s4 = acc_lo(v[b].z, s4); s5 = acc_hi(v[b].z, s5);
            s6 = acc_lo(v[b].w, s6); s7 = acc_hi(v[b].w, s7);
        }
    }
    for (; j + 2 <= deg; j += 2) {
        int off = __ldg(&csr[base + j + half]);
        uint4 v = *reinterpret_cast<const uint4*>(Xq + (size_t)off + coloff);
        s0 = acc_lo(v.x, s0); s1 = acc_hi(v.x, s1);
        s2 = acc_lo(v.y, s2); s3 = acc_hi(v.y, s3);
        s4 = acc_lo(v.z, s4); s5 = acc_hi(v.z, s5);
        s6 = acc_lo(v.w, s6); s7 = acc_hi(v.w, s7);
    }
    if (j < deg) {   // last odd neighbor: only half 0 contributes
        int off = __ldg(&csr[base + j]);
        uint4 v = make_uint4(0, 0, 0, 0);
        if (half == 0)
            v = *reinterpret_cast<const uint4*>(Xq + (size_t)off + coloff);
        s0 = acc_lo(v.x, s0); s1 = acc_hi(v.x, s1);
        s2 = acc_lo(v.y, s2); s3 = acc_hi(v.y, s3);
        s4 = acc_lo(v.z, s4); s5 = acc_hi(v.z, s5);
        s6 = acc_lo(v.w, s6); s7 = acc_hi(v.w, s7);
    }

    // combine the two half-warp partial sums (exact integer add)
    s0 += __shfl_xor_sync(0xffffffffu, s0, 16);
    s1 += __shfl_xor_sync(0xffffffffu, s1, 16);
    s2 += __shfl_xor_sync(0xffffffffu, s2, 16);
    s3 += __shfl_xor_sync(0xffffffffu, s3, 16);
    s4 += __shfl_xor_sync(0xffffffffu, s4, 16);
    s5 += __shfl_xor_sync(0xffffffffu, s5, 16);
    s6 += __shfl_xor_sync(0xffffffffu, s6, 16);
    s7 += __shfl_xor_sync(0xffffffffu, s7, 16);

    if (half == 0) {
        float f = QINV / fmaxf((float)deg, 1.0f);
        float a0 = (float)s0 * f, a1 = (float)s1 * f;
        float a2 = (float)s2 * f, a3 = (float)s3 * f;
        float a4 = (float)s4 * f, a5 = (float)s5 * f;
        float a6 = (float)s6 * f, a7 = (float)s7 * f;

        float h0, l0, h1, l1, h2, l2, h3, l3, h4, l4, h5, l5, h6, l6, h7, l7;
        split1(a0, h0, l0); split1(a1, h1, l1);
        split1(a2, h2, l2); split1(a3, h3, l3);
        split1(a4, h4, l4); split1(a5, h5, l5);
        split1(a6, h6, l6); split1(a7, h7, l7);

        size_t o = (size_t)warp * DIM + coloff;
        *reinterpret_cast<uint4*>(g_ahi + o) =
            make_uint4(pack_bf2(h0, h1), pack_bf2(h2, h3),
                       pack_bf2(h4, h5), pack_bf2(h6, h7));
        *reinterpret_cast<uint4*>(g_alo + o) =
            make_uint4(pack_bf2(l0, l1), pack_bf2(l2, l3),
                       pack_bf2(l4, l5), pack_bf2(l6, l7));
    }
}

// ---------------------------------------------------------------------------
// bf16 3-term tensor-core GEMM + bias + relu (R12-proven, frozen).
// cp.async double-buffered: tile t+1 loads overlap tile t mma.
// ---------------------------------------------------------------------------
__global__ void __launch_bounds__(256)
gemm_bf16_kernel(const __nv_bfloat16* __restrict__ Ahi0,
                 const __nv_bfloat16* __restrict__ Alo0,
                 const __nv_bfloat16* __restrict__ Whi,   // [128 n][256 k]
                 const __nv_bfloat16* __restrict__ Wlo,
                 const float* __restrict__ bias,
                 float* __restrict__ out,
                 __nv_bfloat16* __restrict__ Ohi,
                 __nv_bfloat16* __restrict__ Olo,
                 short* __restrict__ Oq,
                 int n_nodes) {
    extern __shared__ uint32_t dynsmem[];
    __shared__ float bia[128];

    const int tid  = threadIdx.x;
    const int wid  = tid >> 5;
    const int lane = tid & 31;
    const int wm   = wid >> 1;
    const int wn   = wid & 1;
    const int g    = lane >> 2;
    const int tq   = lane & 3;
    const int row0 = blockIdx.x * GEMM_RPB;

    if (tid < 128) bia[tid] = bias[tid];

    float acc[2][8][4];
#pragma unroll
    for (int i = 0; i < 2; i++)
#pragma unroll
        for (int j = 0; j < 8; j++)
#pragma unroll
            for (int c = 0; c < 4; c++) acc[i][j][c] = 0.0f;

    const int r    = tid >> 1;
    const int half = tid & 1;
    const int gr   = row0 + r;
    const bool rok = (gr < n_nodes);
    const int grc  = rok ? gr : (n_nodes - 1);
    const int asz  = rok ? 16 : 0;

    const uint32_t off_u32 = r * AS + half * 8;

    auto issue = [&](int t, uint32_t* buf) {
        const int kt = t * 32;
        const bool agg = (kt >= DIM);
        const int  kb  = kt & (DIM - 1);
        const __nv_bfloat16* __restrict__ Ah = agg ? g_ahi : Ahi0;
        const __nv_bfloat16* __restrict__ Al = agg ? g_alo : Alo0;
        const uint4* ph = reinterpret_cast<const uint4*>(
            Ah + (size_t)grc * DIM + kb) + half * 2;
        const uint4* pl = reinterpret_cast<const uint4*>(
            Al + (size_t)grc * DIM + kb) + half * 2;
        const uint4* qh = reinterpret_cast<const uint4*>(
            Whi + (size_t)r * 2 * DIM + kt) + half * 2;
        const uint4* ql = reinterpret_cast<const uint4*>(
            Wlo + (size_t)r * 2 * DIM + kt) + half * 2;
        uint32_t da = (uint32_t)__cvta_generic_to_shared(buf + off_u32);
        uint32_t dl = (uint32_t)__cvta_generic_to_shared(buf + 128 * AS + off_u32);
        uint32_t dwh = (uint32_t)__cvta_generic_to_shared(buf + 2 * 128 * AS + off_u32);
        uint32_t dwl = (uint32_t)__cvta_generic_to_shared(buf + 3 * 128 * AS + off_u32);
        cp16(da,       ph,     asz);
        cp16(da + 16,  ph + 1, asz);
        cp16(dl,       pl,     asz);
        cp16(dl + 16,  pl + 1, asz);
        cp16(dwh,      qh,     16);
        cp16(dwh + 16, qh + 1, 16);
        cp16(dwl,      ql,     16);
        cp16(dwl + 16, ql + 1, 16);
        asm volatile("cp.async.commit_group;");
    };

    issue(0, dynsmem);

    for (int t = 0; t < 8; t++) {
        uint32_t* buf = dynsmem + (t & 1) * BUFU;
        if (t < 7) {
            issue(t + 1, dynsmem + ((t + 1) & 1) * BUFU);
            asm volatile("cp.async.wait_group 1;");
        } else {
            asm volatile("cp.async.wait_group 0;");
        }
        __syncthreads();

        const uint32_t* a_hi_s = buf;
        const uint32_t* a_lo_s = buf + 128 * AS;
        const uint32_t* w_hi_s = buf + 2 * 128 * AS;
        const uint32_t* w_lo_s = buf + 3 * 128 * AS;

#pragma unroll
        for (int k16 = 0; k16 < 32; k16 += 16) {
            const int kw = (k16 >> 1) + tq;
            uint32_t Afh[2][4], Afl[2][4];
#pragma unroll
            for (int i = 0; i < 2; i++) {
                int r0 = wm * 32 + i * 16 + g;
                Afh[i][0] = a_hi_s[r0 * AS + kw];
                Afh[i][1] = a_hi_s[(r0 + 8) * AS + kw];
                Afh[i][2] = a_hi_s[r0 * AS + kw + 4];
                Afh[i][3] = a_hi_s[(r0 + 8) * AS + kw + 4];
                Afl[i][0] = a_lo_s[r0 * AS + kw];
                Afl[i][1] = a_lo_s[(r0 + 8) * AS + kw];
                Afl[i][2] = a_lo_s[r0 * AS + kw + 4];
                Afl[i][3] = a_lo_s[(r0 + 8) * AS + kw + 4];
            }
#pragma unroll
            for (int j = 0; j < 8; j++) {
                int c = wn * 64 + j * 8 + g;
                uint32_t Bh[2], Bl[2];
                Bh[0] = w_hi_s[c * AS + kw];
                Bh[1] = w_hi_s[c * AS + kw + 4];
                Bl[0] = w_lo_s[c * AS + kw];
                Bl[1] = w_lo_s[c * AS + kw + 4];
#pragma unroll
                for (int i = 0; i < 2; i++) {
                    mma_bf16(acc[i][j], Afh[i], Bh);
                    mma_bf16(acc[i][j], Afh[i], Bl);
                    mma_bf16(acc[i][j], Afl[i], Bh);
                }
            }
        }
        __syncthreads();
    }

    // Epilogue
#pragma unroll
    for (int i = 0; i < 2; i++) {
#pragma unroll
        for (int half_r = 0; half_r < 2; half_r++) {
            int rr = row0 + wm * 32 + i * 16 + half_r * 8 + g;
            if (rr >= n_nodes) continue;
#pragma unroll
            for (int j = 0; j < 8; j++) {
                int col = wn * 64 + j * 8 + 2 * tq;
                float ox = fmaxf(acc[i][j][2 * half_r]     + bia[col], 0.f);
                float oy = fmaxf(acc[i][j][2 * half_r + 1] + bia[col + 1], 0.f);
                if (out)
                    *reinterpret_cast<float2*>(out + (size_t)rr * DIM + col) =
                        make_float2(ox, oy);
                if (Ohi) {
                    float hx, lx, hy, ly;
                    split1(ox, hx, lx); split1(oy, hy, ly);
                    *reinterpret_cast<uint32_t*>(Ohi + (size_t)rr * DIM + col) =
                        pack_bf2(hx, hy);
                    *reinterpret_cast<uint32_t*>(Olo + (size_t)rr * DIM + col) =
                        pack_bf2(lx, ly);
                }
                if (Oq)
                    *reinterpret_cast<uint32_t*>(Oq + (size_t)rr * DIM + col) =
                        pack_q2(ox, oy);
            }
        }
    }
}

// ---------------------------------------------------------------------------
// Launch
// ---------------------------------------------------------------------------
extern "C" void kernel_launch(void* const* d_in, const int* in_sizes, int n_in,
                              void* d_out, int out_size) {
    const float* x  = (const float*)d_in[0];
    const int*   ei = (const int*)d_in[1];
    const float* W1 = (const float*)d_in[2];
    const float* b1 = (const float*)d_in[3];
    const float* W2 = (const float*)d_in[4];
    const float* b2 = (const float*)d_in[5];
    float* out = (float*)d_out;

    const int n_nodes = in_sizes[0] / DIM;
    const int E       = in_sizes[1] / 2;
    const int* src = ei;
    const int* tgt = ei + E;

    __nv_bfloat16 *xhi, *xlo, *hhi, *hlo, *whi, *wlo;
    short* hq;
    cudaGetSymbolAddress((void**)&xhi, g_xhi);
    cudaGetSymbolAddress((void**)&xlo, g_xlo);
    cudaGetSymbolAddress((void**)&hhi, g_hhi);
    cudaGetSymbolAddress((void**)&hlo, g_hlo);
    cudaGetSymbolAddress((void**)&whi, g_wthi);
    cudaGetSymbolAddress((void**)&wlo, g_wtlo);
    cudaGetSymbolAddress((void**)&hq,  g_hq);

    cudaFuncSetAttribute(gemm_bf16_kernel,
                         cudaFuncAttributeMaxDynamicSharedMemorySize, SMEM_DYN);

    const int threads = 256;
    const int n4 = n_nodes * DIM / 4;
    const int pb = (n4 + threads - 1) / threads;
    const int eb = (E + threads - 1) / threads;
    const int nb = (n_nodes + threads - 1) / threads;
    const int ab = ((n_nodes * 32) + threads - 1) / threads;
    const int gb = (n_nodes + GEMM_RPB - 1) / GEMM_RPB;
    const size_t wstride = (size_t)DIM * 2 * DIM;

    prep_kernel<<<pb, threads>>>(x, W1, W2, tgt, E, n_nodes, n4);
    reserve_kernel<<<nb, threads>>>(n_nodes);
    fill_kernel<<<eb, threads>>>(src, tgt, E, n_nodes);

    aggregate_kernel<<<ab, threads>>>(0, n_nodes);
    gemm_bf16_kernel<<<gb, threads, SMEM_DYN>>>(xhi, xlo, whi, wlo, b1,
                                                nullptr, hhi, hlo, hq, n_nodes);

    aggregate_kernel<<<ab, threads>>>(1, n_nodes);
    gemm_bf16_kernel<<<gb, threads, SMEM_DYN>>>(hhi, hlo, whi + wstride,
                                                wlo + wstride, b2, out,
                                                nullptr, nullptr, nullptr,
                                                n_nodes);
}

// round 16
// speedup vs baseline: 1.0136x; 1.0136x over previous
#include <cuda_runtime.h>
#include <cuda_bf16.h>
#include <cstdint>

#define DIM   128
#define MAX_N 50000
#define MAX_E 800000

#define GEMM_RPB 128
#define AS 20                 // smem row stride in u32 words (32 bf16 = 16w + 4 pad)
#define BUFU (4 * 128 * AS)   // u32 per pipeline buffer (a_hi,a_lo,w_hi,w_lo)
#define SMEM_DYN (2 * BUFU * 4)
#define QSCALE 4096.0f
#define QINV   (1.0f / 4096.0f)

// ---------------------------------------------------------------------------
// Scratch (no allocations allowed). g_deg/g_total rely on zero-init at load;
// they are re-zeroed at the end of every launch (layer-2 aggregate).
// ---------------------------------------------------------------------------
__device__ __align__(16) __nv_bfloat16 g_xhi[MAX_N * DIM];
__device__ __align__(16) __nv_bfloat16 g_xlo[MAX_N * DIM];
__device__ __align__(16) __nv_bfloat16 g_hhi[MAX_N * DIM];
__device__ __align__(16) __nv_bfloat16 g_hlo[MAX_N * DIM];
__device__ __align__(16) __nv_bfloat16 g_ahi[MAX_N * DIM];
__device__ __align__(16) __nv_bfloat16 g_alo[MAX_N * DIM];
__device__ __align__(16) short g_xq[MAX_N * DIM];   // int16 features, scale 4096
__device__ __align__(16) short g_hq[MAX_N * DIM];
__device__ __align__(16) __nv_bfloat16 g_wthi[2 * DIM * 2 * DIM]; // [layer][n][k]
__device__ __align__(16) __nv_bfloat16 g_wtlo[2 * DIM * 2 * DIM];
__device__ int g_deg[MAX_N];     // zero at launch start (invariant)
__device__ int g_row[MAX_N];
__device__ int g_pos[MAX_E];
__device__ int g_csr[MAX_E];     // element offsets: src_node * DIM
__device__ int g_total;          // zero at launch start (invariant)

// ---------------------------------------------------------------------------
// Helpers
// ---------------------------------------------------------------------------
__device__ __forceinline__ uint32_t pack_bf2(float a, float b) {
    __nv_bfloat162 t = __floats2bfloat162_rn(a, b);
    return *reinterpret_cast<uint32_t*>(&t);
}
__device__ __forceinline__ void split1(float v, float& hi, float& lo) {
    __nv_bfloat16 h = __float2bfloat16_rn(v);
    hi = __bfloat162float(h);
    lo = v - hi;
}
__device__ __forceinline__ int quant1(float v) {
    return __float2int_rn(fminf(fmaxf(v * QSCALE, -32767.0f), 32767.0f));
}
__device__ __forceinline__ uint32_t pack_q2(float a, float b) {
    return (uint32_t)(quant1(a) & 0xffff) | ((uint32_t)quant1(b) << 16);
}
__device__ __forceinline__ void mma_bf16(float* d, const uint32_t* a,
                                         const uint32_t* b) {
    asm volatile(
        "mma.sync.aligned.m16n8k16.row.col.f32.bf16.bf16.f32 "
        "{%0,%1,%2,%3}, {%4,%5,%6,%7}, {%8,%9}, {%0,%1,%2,%3};"
        : "+f"(d[0]), "+f"(d[1]), "+f"(d[2]), "+f"(d[3])
        : "r"(a[0]), "r"(a[1]), "r"(a[2]), "r"(a[3]), "r"(b[0]), "r"(b[1]));
}
__device__ __forceinline__ void cp16(uint32_t dst_smem, const void* src, int sz) {
    asm volatile("cp.async.cg.shared.global [%0], [%1], 16, %2;"
                 :: "r"(dst_smem), "l"(src), "r"(sz));
}
// s += sign_extend(lo16(v)) : one dp2a;  s += sign_extend(hi16(v)) : one dp2a
__device__ __forceinline__ int acc_lo(uint32_t v, int s) {
    return __dp2a_lo((int)v, 1, s);
}
__device__ __forceinline__ int acc_hi(uint32_t v, int s) {
    return __dp2a_lo((int)v, 256, s);
}

// ---------------------------------------------------------------------------
// Fused prep: degree count (g_deg pre-zeroed invariant) + split x + split W
// ---------------------------------------------------------------------------
__global__ void prep_kernel(const float* __restrict__ X,
                            const float* __restrict__ W1,
                            const float* __restrict__ W2,
                            const int* __restrict__ tgt,
                            int E, int n_nodes, int n4) {
    int i = blockIdx.x * blockDim.x + threadIdx.x;
    if (i < E) {
        int d = tgt[i];
        if ((unsigned)d < (unsigned)n_nodes)
            g_pos[i] = atomicAdd(&g_deg[d], 1);
    }
    if (i < n4) {
        float4 v = reinterpret_cast<const float4*>(X)[i];
        float hx, lx, hy, ly, hz, lz, hw, lw;
        split1(v.x, hx, lx); split1(v.y, hy, ly);
        split1(v.z, hz, lz); split1(v.w, hw, lw);
        reinterpret_cast<uint2*>(g_xhi)[i] = make_uint2(pack_bf2(hx, hy), pack_bf2(hz, hw));
        reinterpret_cast<uint2*>(g_xlo)[i] = make_uint2(pack_bf2(lx, ly), pack_bf2(lz, lw));
        reinterpret_cast<uint2*>(g_xq)[i]  = make_uint2(pack_q2(v.x, v.y), pack_q2(v.z, v.w));
    }
    if (i < 2 * 256 * 128) {
        int layer = i >> 15;
        int idx = i & 32767;
        int k = idx >> 7;
        int n = idx & 127;
        float v = layer ? W2[idx] : W1[idx];
        float hi, lo;
        split1(v, hi, lo);
        size_t o = (size_t)layer * DIM * 2 * DIM + (size_t)n * 2 * DIM + k;
        g_wthi[o] = __float2bfloat16_rn(hi);
        g_wtlo[o] = __float2bfloat16_rn(lo);
    }
}

// ---------------------------------------------------------------------------
// CSR construction
// ---------------------------------------------------------------------------
__global__ void reserve_kernel(int n_nodes) {
    int i = blockIdx.x * blockDim.x + threadIdx.x;
    if (i < n_nodes) g_row[i] = atomicAdd(&g_total, g_deg[i]);
}

__global__ void fill_kernel(const int* __restrict__ src,
                            const int* __restrict__ tgt, int E, int n_nodes) {
    int e = blockIdx.x * blockDim.x + threadIdx.x;
    if (e < E) {
        int d = tgt[e];
        if ((unsigned)d < (unsigned)n_nodes) {
            int s = src[e];
            s = min(max(s, 0), n_nodes - 1);
            g_csr[g_row[d] + g_pos[e]] = s * DIM;   // element offset
        }
    }
}

// ---------------------------------------------------------------------------
// Aggregation (R14-proven structure): one warp per node; int16 gather,
// exact int32 accumulation via dp2a. csr holds element offsets (no IMAD).
// Layer-2 pass (use_h=1) re-zeroes g_deg/g_total to restore launch invariant.
// ---------------------------------------------------------------------------
__global__ void aggregate_kernel(int use_h, int n_nodes) {
    int warp = (blockIdx.x * blockDim.x + threadIdx.x) >> 5;
    int lane = threadIdx.x & 31;
    if (warp >= n_nodes) return;

    const short* __restrict__ Xq = use_h ? g_hq : g_xq;
    const int* __restrict__ csr = g_csr;
    const int base = g_row[warp];
    const int deg  = g_deg[warp];
    const int lo4  = lane * 4;

    if (use_h && lane == 0) {
        g_deg[warp] = 0;                   // restore zero invariant
        if (warp == 0) g_total = 0;
    }

    int s0 = 0, s1 = 0, s2 = 0, s3 = 0;
    int j = 0;
    for (; j + 16 <= deg; j += 16) {
        uint2 v[16];
#pragma unroll
        for (int u = 0; u < 16; u++) {
            int off = __ldg(&csr[base + j + u]);
            v[u] = *reinterpret_cast<const uint2*>(Xq + (size_t)off + lo4);
        }
#pragma unroll
        for (int u = 0; u < 16; u++) {
            s0 = acc_lo(v[u].x, s0);
            s1 = acc_hi(v[u].x, s1);
            s2 = acc_lo(v[u].y, s2);
            s3 = acc_hi(v[u].y, s3);
        }
    }
    if (j + 8 <= deg) {
        uint2 v[8];
#pragma unroll
        for (int u = 0; u < 8; u++) {
            int off = __ldg(&csr[base + j + u]);
            v[u] = *reinterpret_cast<const uint2*>(Xq + (size_t)off + lo4);
        }
#pragma unroll
        for (int u = 0; u < 8; u++) {
            s0 = acc_lo(v[u].x, s0);
            s1 = acc_hi(v[u].x, s1);
            s2 = acc_lo(v[u].y, s2);
            s3 = acc_hi(v[u].y, s3);
        }
        j += 8;
    }
    for (; j < deg; j++) {
        int off = __ldg(&csr[base + j]);
        uint2 v = *reinterpret_cast<const uint2*>(Xq + (size_t)off + lo4);
        s0 = acc_lo(v.x, s0);
        s1 = acc_hi(v.x, s1);
        s2 = acc_lo(v.y, s2);
        s3 = acc_hi(v.y, s3);
    }

    float f = QINV / fmaxf((float)deg, 1.0f);
    float ax = (float)s0 * f, ay = (float)s1 * f;
    float az = (float)s2 * f, aw = (float)s3 * f;

    float hx, lx, hy, ly, hz, lz, hw, lw;
    split1(ax, hx, lx); split1(ay, hy, ly);
    split1(az, hz, lz); split1(aw, hw, lw);
    size_t o4 = ((size_t)warp * DIM + lo4) >> 2;   // uint2 index
    reinterpret_cast<uint2*>(g_ahi)[o4] = make_uint2(pack_bf2(hx, hy), pack_bf2(hz, hw));
    reinterpret_cast<uint2*>(g_alo)[o4] = make_uint2(pack_bf2(lx, ly), pack_bf2(lz, lw));
}

// ---------------------------------------------------------------------------
// bf16 3-term tensor-core GEMM + bias + relu (R12-proven, frozen).
// cp.async double-buffered: tile t+1 loads overlap tile t mma.
// ---------------------------------------------------------------------------
__global__ void __launch_bounds__(256)
gemm_bf16_kernel(const __nv_bfloat16* __restrict__ Ahi0,
                 const __nv_bfloat16* __restrict__ Alo0,
                 const __nv_bfloat16* __restrict__ Whi,   // [128 n][256 k]
                 const __nv_bfloat16* __restrict__ Wlo,
                 const float* __restrict__ bias,
                 float* __restrict__ out,
                 __nv_bfloat16* __restrict__ Ohi,
                 __nv_bfloat16* __restrict__ Olo,
                 short* __restrict__ Oq,
                 int n_nodes) {
    extern __shared__ uint32_t dynsmem[];
    __shared__ float bia[128];

    const int tid  = threadIdx.x;
    const int wid  = tid >> 5;
    const int lane = tid & 31;
    const int wm   = wid >> 1;
    const int wn   = wid & 1;
    const int g    = lane >> 2;
    const int tq   = lane & 3;
    const int row0 = blockIdx.x * GEMM_RPB;

    if (tid < 128) bia[tid] = bias[tid];

    float acc[2][8][4];
#pragma unroll
    for (int i = 0; i < 2; i++)
#pragma unroll
        for (int j = 0; j < 8; j++)
#pragma unroll
            for (int c = 0; c < 4; c++) acc[i][j][c] = 0.0f;

    const int r    = tid >> 1;
    const int half = tid & 1;
    const int gr   = row0 + r;
    const bool rok = (gr < n_nodes);
    const int grc  = rok ? gr : (n_nodes - 1);
    const int asz  = rok ? 16 : 0;

    const uint32_t off_u32 = r * AS + half * 8;

    auto issue = [&](int t, uint32_t* buf) {
        const int kt = t * 32;
        const bool agg = (kt >= DIM);
        const int  kb  = kt & (DIM - 1);
        const __nv_bfloat16* __restrict__ Ah = agg ? g_ahi : Ahi0;
        const __nv_bfloat16* __restrict__ Al = agg ? g_alo : Alo0;
        const uint4* ph = reinterpret_cast<const uint4*>(
            Ah + (size_t)grc * DIM + kb) + half * 2;
        const uint4* pl = reinterpret_cast<const uint4*>(
            Al + (size_t)grc * DIM + kb) + half * 2;
        const uint4* qh = reinterpret_cast<const uint4*>(
            Whi + (size_t)r * 2 * DIM + kt) + half * 2;
        const uint4* ql = reinterpret_cast<const uint4*>(
            Wlo + (size_t)r * 2 * DIM + kt) + half * 2;
        uint32_t da = (uint32_t)__cvta_generic_to_shared(buf + off_u32);
        uint32_t dl = (uint32_t)__cvta_generic_to_shared(buf + 128 * AS + off_u32);
        uint32_t dwh = (uint32_t)__cvta_generic_to_shared(buf + 2 * 128 * AS + off_u32);
        uint32_t dwl = (uint32_t)__cvta_generic_to_shared(buf + 3 * 128 * AS + off_u32);
        cp16(da,       ph,     asz);
        cp16(da + 16,  ph + 1, asz);
        cp16(dl,       pl,     asz);
        cp16(dl + 16,  pl + 1, asz);
        cp16(dwh,      qh,     16);
        cp16(dwh + 16, qh + 1, 16);
        cp16(dwl,      ql,     16);
        cp16(dwl + 16, ql + 1, 16);
        asm volatile("cp.async.commit_group;");
    };

    issue(0, dynsmem);

    for (int t = 0; t < 8; t++) {
        uint32_t* buf = dynsmem + (t & 1) * BUFU;
        if (t < 7) {
            issue(t + 1, dynsmem + ((t + 1) & 1) * BUFU);
            asm volatile("cp.async.wait_group 1;");
        } else {
            asm volatile("cp.async.wait_group 0;");
        }
        __syncthreads();

        const uint32_t* a_hi_s = buf;
        const uint32_t* a_lo_s = buf + 128 * AS;
        const uint32_t* w_hi_s = buf + 2 * 128 * AS;
        const uint32_t* w_lo_s = buf + 3 * 128 * AS;

#pragma unroll
        for (int k16 = 0; k16 < 32; k16 += 16) {
            const int kw = (k16 >> 1) + tq;
            uint32_t Afh[2][4], Afl[2][4];
#pragma unroll
            for (int i = 0; i < 2; i++) {
                int r0 = wm * 32 + i * 16 + g;
                Afh[i][0] = a_hi_s[r0 * AS + kw];
                Afh[i][1] = a_hi_s[(r0 + 8) * AS + kw];
                Afh[i][2] = a_hi_s[r0 * AS + kw + 4];
                Afh[i][3] = a_hi_s[(r0 + 8) * AS + kw + 4];
                Afl[i][0] = a_lo_s[r0 * AS + kw];
                Afl[i][1] = a_lo_s[(r0 + 8) * AS + kw];
                Afl[i][2] = a_lo_s[r0 * AS + kw + 4];
                Afl[i][3] = a_lo_s[(r0 + 8) * AS + kw + 4];
            }
#pragma unroll
            for (int j = 0; j < 8; j++) {
                int c = wn * 64 + j * 8 + g;
                uint32_t Bh[2], Bl[2];
                Bh[0] = w_hi_s[c * AS + kw];
                Bh[1] = w_hi_s[c * AS + kw + 4];
                Bl[0] = w_lo_s[c * AS + kw];
                Bl[1] = w_lo_s[c * AS + kw + 4];
#pragma unroll
                for (int i = 0; i < 2; i++) {
                    mma_bf16(acc[i][j], Afh[i], Bh);
                    mma_bf16(acc[i][j], Afh[i], Bl);
                    mma_bf16(acc[i][j], Afl[i], Bh);
                }
            }
        }
        __syncthreads();
    }

    // Epilogue
#pragma unroll
    for (int i = 0; i < 2; i++) {
#pragma unroll
        for (int half_r = 0; half_r < 2; half_r++) {
            int rr = row0 + wm * 32 + i * 16 + half_r * 8 + g;
            if (rr >= n_nodes) continue;
#pragma unroll
            for (int j = 0; j < 8; j++) {
                int col = wn * 64 + j * 8 + 2 * tq;
                float ox = fmaxf(acc[i][j][2 * half_r]     + bia[col], 0.f);
                float oy = fmaxf(acc[i][j][2 * half_r + 1] + bia[col + 1], 0.f);
                if (out)
                    *reinterpret_cast<float2*>(out + (size_t)rr * DIM + col) =
                        make_float2(ox, oy);
                if (Ohi) {
                    float hx, lx, hy, ly;
                    split1(ox, hx, lx); split1(oy, hy, ly);
                    *reinterpret_cast<uint32_t*>(Ohi + (size_t)rr * DIM + col) =
                        pack_bf2(hx, hy);
                    *reinterpret_cast<uint32_t*>(Olo + (size_t)rr * DIM + col) =
                        pack_bf2(lx, ly);
                }
                if (Oq)
                    *reinterpret_cast<uint32_t*>(Oq + (size_t)rr * DIM + col) =
                        pack_q2(ox, oy);
            }
        }
    }
}

// ---------------------------------------------------------------------------
// Launch
// ---------------------------------------------------------------------------
extern "C" void kernel_launch(void* const* d_in, const int* in_sizes, int n_in,
                              void* d_out, int out_size) {
    const float* x  = (const float*)d_in[0];
    const int*   ei = (const int*)d_in[1];
    const float* W1 = (const float*)d_in[2];
    const float* b1 = (const float*)d_in[3];
    const float* W2 = (const float*)d_in[4];
    const float* b2 = (const float*)d_in[5];
    float* out = (float*)d_out;

    const int n_nodes = in_sizes[0] / DIM;
    const int E       = in_sizes[1] / 2;
    const int* src = ei;
    const int* tgt = ei + E;

    __nv_bfloat16 *xhi, *xlo, *hhi, *hlo, *whi, *wlo;
    short* hq;
    cudaGetSymbolAddress((void**)&xhi, g_xhi);
    cudaGetSymbolAddress((void**)&xlo, g_xlo);
    cudaGetSymbolAddress((void**)&hhi, g_hhi);
    cudaGetSymbolAddress((void**)&hlo, g_hlo);
    cudaGetSymbolAddress((void**)&whi, g_wthi);
    cudaGetSymbolAddress((void**)&wlo, g_wtlo);
    cudaGetSymbolAddress((void**)&hq,  g_hq);

    cudaFuncSetAttribute(gemm_bf16_kernel,
                         cudaFuncAttributeMaxDynamicSharedMemorySize, SMEM_DYN);

    const int threads = 256;
    const int n4 = n_nodes * DIM / 4;
    const int pb = (n4 + threads - 1) / threads;
    const int eb = (E + threads - 1) / threads;
    const int nb = (n_nodes + threads - 1) / threads;
    const int ab = ((n_nodes * 32) + threads - 1) / threads;
    const int gb = (n_nodes + GEMM_RPB - 1) / GEMM_RPB;
    const size_t wstride = (size_t)DIM * 2 * DIM;

    prep_kernel<<<pb, threads>>>(x, W1, W2, tgt, E, n_nodes, n4);
    reserve_kernel<<<nb, threads>>>(n_nodes);
    fill_kernel<<<eb, threads>>>(src, tgt, E, n_nodes);

    aggregate_kernel<<<ab, threads>>>(0, n_nodes);
    gemm_bf16_kernel<<<gb, threads, SMEM_DYN>>>(xhi, xlo, whi, wlo, b1,
                                                nullptr, hhi, hlo, hq, n_nodes);

    aggregate_kernel<<<ab, threads>>>(1, n_nodes);
    gemm_bf16_kernel<<<gb, threads, SMEM_DYN>>>(hhi, hlo, whi + wstride,
                                                wlo + wstride, b2, out,
                                                nullptr, nullptr, nullptr,
                                                n_nodes);
}

// round 17
// speedup vs baseline: 1.2802x; 1.2630x over previous
#include <cuda_runtime.h>
#include <cuda_bf16.h>
#include <cstdint>

#define DIM   128
#define MAX_N 50000
#define MAX_E 800000

#define GEMM_RPB 128
#define AS 20                 // smem row stride in u32 words (32 bf16 = 16w + 4 pad)
#define BUFU (4 * 128 * AS)   // u32 per pipeline buffer (a_hi,a_lo,w_hi,w_lo)
#define SMEM_DYN (2 * BUFU * 4)
#define QSCALE 4096.0f
#define QINV   (1.0f / 4096.0f)

// ---------------------------------------------------------------------------
// Scratch (no allocations allowed). g_deg/g_total rely on zero-init at load;
// they are re-zeroed at the end of every launch (layer-2 aggregate).
// ---------------------------------------------------------------------------
__device__ __align__(16) __nv_bfloat16 g_xhi[MAX_N * DIM];
__device__ __align__(16) __nv_bfloat16 g_xlo[MAX_N * DIM];
__device__ __align__(16) __nv_bfloat16 g_hhi[MAX_N * DIM];
__device__ __align__(16) __nv_bfloat16 g_hlo[MAX_N * DIM];
__device__ __align__(16) __nv_bfloat16 g_ahi[MAX_N * DIM];
__device__ __align__(16) __nv_bfloat16 g_alo[MAX_N * DIM];
__device__ __align__(16) short g_xq[MAX_N * DIM];   // int16 features, scale 4096
__device__ __align__(16) short g_hq[MAX_N * DIM];
__device__ __align__(16) __nv_bfloat16 g_wthi[2 * DIM * 2 * DIM]; // [layer][n][k]
__device__ __align__(16) __nv_bfloat16 g_wtlo[2 * DIM * 2 * DIM];
__device__ int g_deg[MAX_N];     // zero at launch start (invariant)
__device__ int g_row[MAX_N];
__device__ int g_pos[MAX_E];
__device__ int g_csr[MAX_E];
__device__ int g_total;          // zero at launch start (invariant)

// ---------------------------------------------------------------------------
// Helpers
// ---------------------------------------------------------------------------
__device__ __forceinline__ uint32_t pack_bf2(float a, float b) {
    __nv_bfloat162 t = __floats2bfloat162_rn(a, b);
    return *reinterpret_cast<uint32_t*>(&t);
}
__device__ __forceinline__ void split1(float v, float& hi, float& lo) {
    __nv_bfloat16 h = __float2bfloat16_rn(v);
    hi = __bfloat162float(h);
    lo = v - hi;
}
__device__ __forceinline__ int quant1(float v) {
    return __float2int_rn(fminf(fmaxf(v * QSCALE, -32767.0f), 32767.0f));
}
__device__ __forceinline__ uint32_t pack_q2(float a, float b) {
    return (uint32_t)(quant1(a) & 0xffff) | ((uint32_t)quant1(b) << 16);
}
__device__ __forceinline__ void mma_bf16(float* d, const uint32_t* a,
                                         const uint32_t* b) {
    asm volatile(
        "mma.sync.aligned.m16n8k16.row.col.f32.bf16.bf16.f32 "
        "{%0,%1,%2,%3}, {%4,%5,%6,%7}, {%8,%9}, {%0,%1,%2,%3};"
        : "+f"(d[0]), "+f"(d[1]), "+f"(d[2]), "+f"(d[3])
        : "r"(a[0]), "r"(a[1]), "r"(a[2]), "r"(a[3]), "r"(b[0]), "r"(b[1]));
}
__device__ __forceinline__ void cp16(uint32_t dst_smem, const void* src, int sz) {
    asm volatile("cp.async.cg.shared.global [%0], [%1], 16, %2;"
                 :: "r"(dst_smem), "l"(src), "r"(sz));
}
// s += sign_extend(lo16(v)) : one dp2a;  s += sign_extend(hi16(v)) : one dp2a
__device__ __forceinline__ int acc_lo(uint32_t v, int s) {
    return __dp2a_lo((int)v, 1, s);
}
__device__ __forceinline__ int acc_hi(uint32_t v, int s) {
    return __dp2a_lo((int)v, 256, s);
}

// ---------------------------------------------------------------------------
// Fused prep: degree count (g_deg pre-zeroed invariant) + split x + split W
// ---------------------------------------------------------------------------
__global__ void prep_kernel(const float* __restrict__ X,
                            const float* __restrict__ W1,
                            const float* __restrict__ W2,
                            const int* __restrict__ tgt,
                            int E, int n_nodes, int n4) {
    int i = blockIdx.x * blockDim.x + threadIdx.x;
    if (i < E) {
        int d = tgt[i];
        if ((unsigned)d < (unsigned)n_nodes)
            g_pos[i] = atomicAdd(&g_deg[d], 1);
    }
    if (i < n4) {
        float4 v = reinterpret_cast<const float4*>(X)[i];
        float hx, lx, hy, ly, hz, lz, hw, lw;
        split1(v.x, hx, lx); split1(v.y, hy, ly);
        split1(v.z, hz, lz); split1(v.w, hw, lw);
        reinterpret_cast<uint2*>(g_xhi)[i] = make_uint2(pack_bf2(hx, hy), pack_bf2(hz, hw));
        reinterpret_cast<uint2*>(g_xlo)[i] = make_uint2(pack_bf2(lx, ly), pack_bf2(lz, lw));
        reinterpret_cast<uint2*>(g_xq)[i]  = make_uint2(pack_q2(v.x, v.y), pack_q2(v.z, v.w));
    }
    if (i < 2 * 256 * 128) {
        int layer = i >> 15;
        int idx = i & 32767;
        int k = idx >> 7;
        int n = idx & 127;
        float v = layer ? W2[idx] : W1[idx];
        float hi, lo;
        split1(v, hi, lo);
        size_t o = (size_t)layer * DIM * 2 * DIM + (size_t)n * 2 * DIM + k;
        g_wthi[o] = __float2bfloat16_rn(hi);
        g_wtlo[o] = __float2bfloat16_rn(lo);
    }
}

// ---------------------------------------------------------------------------
// CSR construction
// ---------------------------------------------------------------------------
__global__ void reserve_kernel(int n_nodes) {
    int i = blockIdx.x * blockDim.x + threadIdx.x;
    if (i < n_nodes) g_row[i] = atomicAdd(&g_total, g_deg[i]);
}

__global__ void fill_kernel(const int* __restrict__ src,
                            const int* __restrict__ tgt, int E, int n_nodes) {
    int e = blockIdx.x * blockDim.x + threadIdx.x;
    if (e < E) {
        int d = tgt[e];
        if ((unsigned)d < (unsigned)n_nodes) {
            int s = src[e];
            s = min(max(s, 0), n_nodes - 1);
            g_csr[g_row[d] + g_pos[e]] = s;
        }
    }
}

// ---------------------------------------------------------------------------
// Aggregation: one warp per node; int16 gather, exact int32 accumulation.
// dp2a fuses sign-extract + add into one op (alu-pipe pressure -> fma pipe).
// Layer-2 pass (use_h=1) re-zeroes g_deg/g_total to restore launch invariant.
// ---------------------------------------------------------------------------
__global__ void aggregate_kernel(int use_h, int n_nodes) {
    int warp = (blockIdx.x * blockDim.x + threadIdx.x) >> 5;
    int lane = threadIdx.x & 31;
    if (warp >= n_nodes) return;

    const short* __restrict__ Xq = use_h ? g_hq : g_xq;
    const int* __restrict__ csr = g_csr;
    const int base = g_row[warp];
    const int deg  = g_deg[warp];
    const int lo4  = lane * 4;

    if (use_h && lane == 0) {
        g_deg[warp] = 0;                   // restore zero invariant
        if (warp == 0) g_total = 0;
    }

    int s0 = 0, s1 = 0, s2 = 0, s3 = 0;
    int j = 0;
    for (; j + 16 <= deg; j += 16) {
        uint2 v[16];
#pragma unroll
        for (int u = 0; u < 16; u++) {
            int s = __ldg(&csr[base + j + u]);
            v[u] = *reinterpret_cast<const uint2*>(Xq + (size_t)s * DIM + lo4);
        }
#pragma unroll
        for (int u = 0; u < 16; u++) {
            s0 = acc_lo(v[u].x, s0);
            s1 = acc_hi(v[u].x, s1);
            s2 = acc_lo(v[u].y, s2);
            s3 = acc_hi(v[u].y, s3);
        }
    }
    if (j + 8 <= deg) {
        uint2 v[8];
#pragma unroll
        for (int u = 0; u < 8; u++) {
            int s = __ldg(&csr[base + j + u]);
            v[u] = *reinterpret_cast<const uint2*>(Xq + (size_t)s * DIM + lo4);
        }
#pragma unroll
        for (int u = 0; u < 8; u++) {
            s0 = acc_lo(v[u].x, s0);
            s1 = acc_hi(v[u].x, s1);
            s2 = acc_lo(v[u].y, s2);
            s3 = acc_hi(v[u].y, s3);
        }
        j += 8;
    }
    for (; j < deg; j++) {
        int s = __ldg(&csr[base + j]);
        uint2 v = *reinterpret_cast<const uint2*>(Xq + (size_t)s * DIM + lo4);
        s0 = acc_lo(v.x, s0);
        s1 = acc_hi(v.x, s1);
        s2 = acc_lo(v.y, s2);
        s3 = acc_hi(v.y, s3);
    }

    float f = QINV / fmaxf((float)deg, 1.0f);
    float ax = (float)s0 * f, ay = (float)s1 * f;
    float az = (float)s2 * f, aw = (float)s3 * f;

    float hx, lx, hy, ly, hz, lz, hw, lw;
    split1(ax, hx, lx); split1(ay, hy, ly);
    split1(az, hz, lz); split1(aw, hw, lw);
    size_t o4 = ((size_t)warp * DIM + lo4) >> 2;   // uint2 index
    reinterpret_cast<uint2*>(g_ahi)[o4] = make_uint2(pack_bf2(hx, hy), pack_bf2(hz, hw));
    reinterpret_cast<uint2*>(g_alo)[o4] = make_uint2(pack_bf2(lx, ly), pack_bf2(lz, lw));
}

// ---------------------------------------------------------------------------
// bf16 3-term tensor-core GEMM + bias + relu (R12-proven, frozen).
// cp.async double-buffered: tile t+1 loads overlap tile t mma.
// ---------------------------------------------------------------------------
__global__ void __launch_bounds__(256)
gemm_bf16_kernel(const __nv_bfloat16* __restrict__ Ahi0,
                 const __nv_bfloat16* __restrict__ Alo0,
                 const __nv_bfloat16* __restrict__ Whi,   // [128 n][256 k]
                 const __nv_bfloat16* __restrict__ Wlo,
                 const float* __restrict__ bias,
                 float* __restrict__ out,
                 __nv_bfloat16* __restrict__ Ohi,
                 __nv_bfloat16* __restrict__ Olo,
                 short* __restrict__ Oq,
                 int n_nodes) {
    extern __shared__ uint32_t dynsmem[];
    __shared__ float bia[128];

    const int tid  = threadIdx.x;
    const int wid  = tid >> 5;
    const int lane = tid & 31;
    const int wm   = wid >> 1;
    const int wn   = wid & 1;
    const int g    = lane >> 2;
    const int tq   = lane & 3;
    const int row0 = blockIdx.x * GEMM_RPB;

    if (tid < 128) bia[tid] = bias[tid];

    float acc[2][8][4];
#pragma unroll
    for (int i = 0; i < 2; i++)
#pragma unroll
        for (int j = 0; j < 8; j++)
#pragma unroll
            for (int c = 0; c < 4; c++) acc[i][j][c] = 0.0f;

    const int r    = tid >> 1;
    const int half = tid & 1;
    const int gr   = row0 + r;
    const bool rok = (gr < n_nodes);
    const int grc  = rok ? gr : (n_nodes - 1);
    const int asz  = rok ? 16 : 0;

    const uint32_t off_u32 = r * AS + half * 8;

    auto issue = [&](int t, uint32_t* buf) {
        const int kt = t * 32;
        const bool agg = (kt >= DIM);
        const int  kb  = kt & (DIM - 1);
        const __nv_bfloat16* __restrict__ Ah = agg ? g_ahi : Ahi0;
        const __nv_bfloat16* __restrict__ Al = agg ? g_alo : Alo0;
        const uint4* ph = reinterpret_cast<const uint4*>(
            Ah + (size_t)grc * DIM + kb) + half * 2;
        const uint4* pl = reinterpret_cast<const uint4*>(
            Al + (size_t)grc * DIM + kb) + half * 2;
        const uint4* qh = reinterpret_cast<const uint4*>(
            Whi + (size_t)r * 2 * DIM + kt) + half * 2;
        const uint4* ql = reinterpret_cast<const uint4*>(
            Wlo + (size_t)r * 2 * DIM + kt) + half * 2;
        uint32_t da = (uint32_t)__cvta_generic_to_shared(buf + off_u32);
        uint32_t dl = (uint32_t)__cvta_generic_to_shared(buf + 128 * AS + off_u32);
        uint32_t dwh = (uint32_t)__cvta_generic_to_shared(buf + 2 * 128 * AS + off_u32);
        uint32_t dwl = (uint32_t)__cvta_generic_to_shared(buf + 3 * 128 * AS + off_u32);
        cp16(da,       ph,     asz);
        cp16(da + 16,  ph + 1, asz);
        cp16(dl,       pl,     asz);
        cp16(dl + 16,  pl + 1, asz);
        cp16(dwh,      qh,     16);
        cp16(dwh + 16, qh + 1, 16);
        cp16(dwl,      ql,     16);
        cp16(dwl + 16, ql + 1, 16);
        asm volatile("cp.async.commit_group;");
    };

    issue(0, dynsmem);

    for (int t = 0; t < 8; t++) {
        uint32_t* buf = dynsmem + (t & 1) * BUFU;
        if (t < 7) {
            issue(t + 1, dynsmem + ((t + 1) & 1) * BUFU);
            asm volatile("cp.async.wait_group 1;");
        } else {
            asm volatile("cp.async.wait_group 0;");
        }
        __syncthreads();

        const uint32_t* a_hi_s = buf;
        const uint32_t* a_lo_s = buf + 128 * AS;
        const uint32_t* w_hi_s = buf + 2 * 128 * AS;
        const uint32_t* w_lo_s = buf + 3 * 128 * AS;

#pragma unroll
        for (int k16 = 0; k16 < 32; k16 += 16) {
            const int kw = (k16 >> 1) + tq;
            uint32_t Afh[2][4], Afl[2][4];
#pragma unroll
            for (int i = 0; i < 2; i++) {
                int r0 = wm * 32 + i * 16 + g;
                Afh[i][0] = a_hi_s[r0 * AS + kw];
                Afh[i][1] = a_hi_s[(r0 + 8) * AS + kw];
                Afh[i][2] = a_hi_s[r0 * AS + kw + 4];
                Afh[i][3] = a_hi_s[(r0 + 8) * AS + kw + 4];
                Afl[i][0] = a_lo_s[r0 * AS + kw];
                Afl[i][1] = a_lo_s[(r0 + 8) * AS + kw];
                Afl[i][2] = a_lo_s[r0 * AS + kw + 4];
                Afl[i][3] = a_lo_s[(r0 + 8) * AS + kw + 4];
            }
#pragma unroll
            for (int j = 0; j < 8; j++) {
                int c = wn * 64 + j * 8 + g;
                uint32_t Bh[2], Bl[2];
                Bh[0] = w_hi_s[c * AS + kw];
                Bh[1] = w_hi_s[c * AS + kw + 4];
                Bl[0] = w_lo_s[c * AS + kw];
                Bl[1] = w_lo_s[c * AS + kw + 4];
#pragma unroll
                for (int i = 0; i < 2; i++) {
                    mma_bf16(acc[i][j], Afh[i], Bh);
                    mma_bf16(acc[i][j], Afh[i], Bl);
                    mma_bf16(acc[i][j], Afl[i], Bh);
                }
            }
        }
        __syncthreads();
    }

    // Epilogue
#pragma unroll
    for (int i = 0; i < 2; i++) {
#pragma unroll
        for (int half_r = 0; half_r < 2; half_r++) {
            int rr = row0 + wm * 32 + i * 16 + half_r * 8 + g;
            if (rr >= n_nodes) continue;
#pragma unroll
            for (int j = 0; j < 8; j++) {
                int col = wn * 64 + j * 8 + 2 * tq;
                float ox = fmaxf(acc[i][j][2 * half_r]     + bia[col], 0.f);
                float oy = fmaxf(acc[i][j][2 * half_r + 1] + bia[col + 1], 0.f);
                if (out)
                    *reinterpret_cast<float2*>(out + (size_t)rr * DIM + col) =
                        make_float2(ox, oy);
                if (Ohi) {
                    float hx, lx, hy, ly;
                    split1(ox, hx, lx); split1(oy, hy, ly);
                    *reinterpret_cast<uint32_t*>(Ohi + (size_t)rr * DIM + col) =
                        pack_bf2(hx, hy);
                    *reinterpret_cast<uint32_t*>(Olo + (size_t)rr * DIM + col) =
                        pack_bf2(lx, ly);
                }
                if (Oq)
                    *reinterpret_cast<uint32_t*>(Oq + (size_t)rr * DIM + col) =
                        pack_q2(ox, oy);
            }
        }
    }
}

// ---------------------------------------------------------------------------
// Launch
// ---------------------------------------------------------------------------
extern "C" void kernel_launch(void* const* d_in, const int* in_sizes, int n_in,
                              void* d_out, int out_size) {
    const float* x  = (const float*)d_in[0];
    const int*   ei = (const int*)d_in[1];
    const float* W1 = (const float*)d_in[2];
    const float* b1 = (const float*)d_in[3];
    const float* W2 = (const float*)d_in[4];
    const float* b2 = (const float*)d_in[5];
    float* out = (float*)d_out;

    const int n_nodes = in_sizes[0] / DIM;
    const int E       = in_sizes[1] / 2;
    const int* src = ei;
    const int* tgt = ei + E;

    __nv_bfloat16 *xhi, *xlo, *hhi, *hlo, *whi, *wlo;
    short* hq;
    cudaGetSymbolAddress((void**)&xhi, g_xhi);
    cudaGetSymbolAddress((void**)&xlo, g_xlo);
    cudaGetSymbolAddress((void**)&hhi, g_hhi);
    cudaGetSymbolAddress((void**)&hlo, g_hlo);
    cudaGetSymbolAddress((void**)&whi, g_wthi);
    cudaGetSymbolAddress((void**)&wlo, g_wtlo);
    cudaGetSymbolAddress((void**)&hq,  g_hq);

    cudaFuncSetAttribute(gemm_bf16_kernel,
                         cudaFuncAttributeMaxDynamicSharedMemorySize, SMEM_DYN);

    const int threads = 256;
    const int n4 = n_nodes * DIM / 4;
    const int pb = (n4 + threads - 1) / threads;
    const int eb = (E + threads - 1) / threads;
    const int nb = (n_nodes + threads - 1) / threads;
    const int ab = ((n_nodes * 32) + threads - 1) / threads;
    const int gb = (n_nodes + GEMM_RPB - 1) / GEMM_RPB;
    const size_t wstride = (size_t)DIM * 2 * DIM;

    prep_kernel<<<pb, threads>>>(x, W1, W2, tgt, E, n_nodes, n4);
    reserve_kernel<<<nb, threads>>>(n_nodes);
    fill_kernel<<<eb, threads>>>(src, tgt, E, n_nodes);

    aggregate_kernel<<<ab, threads>>>(0, n_nodes);
    gemm_bf16_kernel<<<gb, threads, SMEM_DYN>>>(xhi, xlo, whi, wlo, b1,
                                                nullptr, hhi, hlo, hq, n_nodes);

    aggregate_kernel<<<ab, threads>>>(1, n_nodes);
    gemm_bf16_kernel<<<gb, threads, SMEM_DYN>>>(hhi, hlo, whi + wstride,
                                                wlo + wstride, b2, out,
                                                nullptr, nullptr, nullptr,
                                                n_nodes);
}